// round 1
// baseline (speedup 1.0000x reference)
#include <cuda_runtime.h>
#include <math.h>

#define BATCH 2
#define SEQ   2048
#define EMB   1024
#define NH    16
#define HD    64
#define MROWS (BATCH * SEQ)   // 4096

// ---------------- scratch (device globals; no allocations allowed) ----------
__device__ float g_Qp[(size_t)BATCH * NH * SEQ * HD];   // [B,H,S,D]
__device__ float g_Kp[(size_t)BATCH * NH * SEQ * HD];
__device__ float g_Vp[(size_t)BATCH * NH * SEQ * HD];
__device__ float g_attn[(size_t)BATCH * SEQ * EMB];     // [B,S,E] pre-out-proj
__device__ float g_maskf[BATCH * SEQ];                  // additive mask (-inf / 0)

// ---------------- mask canonicalization -------------------------------------
// The harness may hand the bool mask to us as u8, i32, or f32. Detect
// deterministically: scan the first 1024 32-bit words (4096 bytes, in-bounds
// for every candidate layout).
//   i32 0/1  -> every word in {0,1}
//   f32 0/1  -> every word in {0, 0x3F800000}
//   u8 0/1   -> words are 4 packed bools; essentially surely neither of above
__global__ void prep_mask_kernel(const void* __restrict__ raw) {
    __shared__ int s_not01, s_notf;
    const int t = threadIdx.x;
    if (t == 0) { s_not01 = 0; s_notf = 0; }
    __syncthreads();
    const unsigned int* w = (const unsigned int*)raw;
    for (int i = t; i < (BATCH * SEQ) / 4; i += blockDim.x) {
        unsigned int v = w[i];
        if (v != 0u && v != 1u)          s_not01 = 1;
        if (v != 0u && v != 0x3F800000u) s_notf  = 1;
    }
    __syncthreads();
    const int mode = s_not01 ? (s_notf ? 0 : 2) : 1;  // 0=u8 1=i32 2=f32
    for (int i = t; i < BATCH * SEQ; i += blockDim.x) {
        bool mset;
        if (mode == 1)      mset = ((const int*)raw)[i] != 0;
        else if (mode == 2) mset = ((const float*)raw)[i] != 0.0f;
        else                mset = ((const unsigned char*)raw)[i] != 0;
        g_maskf[i] = mset ? -INFINITY : 0.0f;
    }
}

// ---------------- SGEMM: C = A @ B^T + bias ---------------------------------
// A: [M,K] row-major, B: [N,K] row-major (nn.Linear weight) -> "NT" gemm,
// both operands K-contiguous. 128x128x16 tiles, 256 threads, 8x8 microtile.
// out_mode 0: C[m][n] row-major.  out_mode 1: write [B,H,S,D] head-split.
#define GBM 128
#define GBN 128
#define GBK 16

__global__ __launch_bounds__(256)
void gemm_nt_kernel(const float* __restrict__ A, const float* __restrict__ B,
                    const float* __restrict__ bias, float* __restrict__ C,
                    int M, int N, int K, int out_mode)
{
    __shared__ float As[GBK][GBM + 4];
    __shared__ float Bs[GBK][GBN + 4];

    const int bm = blockIdx.y * GBM;
    const int bn = blockIdx.x * GBN;
    const int tid = threadIdx.x;

    // warp/lane tiling chosen for conflict-free smem reads:
    // rows: 4 addresses/warp, 8-lane broadcast; cols: 8 distinct 4-word groups.
    const int warp = tid >> 5;
    const int lane = tid & 31;
    const int wr = warp & 3;          // 0..3  (32 rows each)
    const int wc = warp >> 2;         // 0..1  (64 cols each)
    const int lr = lane & 3;          // 0..3
    const int lc = lane >> 2;         // 0..7
    const int tr = wr * 32 + lr * 8;              // rows tr..tr+7
    const int tc = wc * 64 + lc * 4;              // cols tc..tc+3, tc+32..tc+35

    float acc[8][8];
#pragma unroll
    for (int i = 0; i < 8; i++)
#pragma unroll
        for (int j = 0; j < 8; j++) acc[i][j] = 0.0f;

    for (int k0 = 0; k0 < K; k0 += GBK) {
#pragma unroll
        for (int l = 0; l < 2; l++) {
            int idx = tid + l * 256;          // 0..511
            int row = idx >> 2;               // 0..127
            int kq  = (idx & 3) * 4;          // 0,4,8,12
            float4 va = *(const float4*)&A[(size_t)(bm + row) * K + k0 + kq];
            As[kq + 0][row] = va.x; As[kq + 1][row] = va.y;
            As[kq + 2][row] = va.z; As[kq + 3][row] = va.w;
            float4 vb = *(const float4*)&B[(size_t)(bn + row) * K + k0 + kq];
            Bs[kq + 0][row] = vb.x; Bs[kq + 1][row] = vb.y;
            Bs[kq + 2][row] = vb.z; Bs[kq + 3][row] = vb.w;
        }
        __syncthreads();
#pragma unroll
        for (int k = 0; k < GBK; k++) {
            float a[8], b[8];
            *(float4*)&a[0] = *(const float4*)&As[k][tr];
            *(float4*)&a[4] = *(const float4*)&As[k][tr + 4];
            *(float4*)&b[0] = *(const float4*)&Bs[k][tc];
            *(float4*)&b[4] = *(const float4*)&Bs[k][tc + 32];
#pragma unroll
            for (int i = 0; i < 8; i++)
#pragma unroll
                for (int j = 0; j < 8; j++)
                    acc[i][j] += a[i] * b[j];
        }
        __syncthreads();
    }

#pragma unroll
    for (int i = 0; i < 8; i++) {
        const int m = bm + tr + i;
        const int bi = m >> 11;       // batch (SEQ = 2048)
        const int s  = m & (SEQ - 1);
#pragma unroll
        for (int j = 0; j < 8; j++) {
            const int n = bn + tc + ((j < 4) ? j : 28 + j);
            const float val = acc[i][j] + bias[n];
            if (out_mode == 0) {
                C[(size_t)m * N + n] = val;
            } else {
                const int h = n >> 6, d = n & (HD - 1);
                C[(((size_t)(bi * NH + h)) * SEQ + s) * HD + d] = val;
            }
        }
    }
}

// ---------------- flash attention (fp32, online softmax) --------------------
// Block: one (b, h, 64-row q tile), 256 threads.
// Thread (r = tid>>2, c = tid&3) owns q-row r; the 4 c-threads of a row are
// adjacent lanes -> shfl row reductions. Score cols j = 4*jj + c, output cols
// d = 16*i + 4*c + w. With smem stride 68 every LDS.128 below is verified
// bank-conflict-free.
#define ASTR 68
#define ATTN_SMEM (4 * 64 * ASTR * 4)   // Qs, Ks, Vs, Ps = 69632 B

__global__ __launch_bounds__(256)
void attn_kernel()
{
    extern __shared__ float sm[];
    float* Qs = sm;
    float* Ks = Qs + 64 * ASTR;
    float* Vs = Ks + 64 * ASTR;
    float* Ps = Vs + 64 * ASTR;

    const int b  = blockIdx.z;
    const int h  = blockIdx.y;
    const int q0 = blockIdx.x * 64;
    const int tid = threadIdx.x;
    const int r = tid >> 2;
    const int c = tid & 3;

    const float* Qg = &g_Qp[(((size_t)(b * NH + h)) * SEQ + q0) * HD];
    const float* Kg = &g_Kp[((size_t)(b * NH + h)) * SEQ * HD];
    const float* Vg = &g_Vp[((size_t)(b * NH + h)) * SEQ * HD];
    const float* maskb = &g_maskf[b * SEQ];

    for (int i = tid; i < 64 * 16; i += 256) {
        int row = i >> 4, c4 = (i & 15) * 4;
        *(float4*)&Qs[row * ASTR + c4] = *(const float4*)&Qg[row * 64 + c4];
    }

    float O[16];
#pragma unroll
    for (int i = 0; i < 16; i++) O[i] = 0.0f;
    // -FLT_MAX (not -inf) so an all-masked key tile can't NaN-poison state.
    float mrow = -3.402823466e38f;
    float lrow = 0.0f;

    for (int kt = 0; kt < SEQ / 64; kt++) {
        const int k0 = kt * 64;
        __syncthreads();   // prior tile fully consumed (also covers Q load)
        const float* Kt = Kg + (size_t)k0 * 64;
        const float* Vt = Vg + (size_t)k0 * 64;
        for (int i = tid; i < 64 * 16; i += 256) {
            int row = i >> 4, c4 = (i & 15) * 4;
            *(float4*)&Ks[row * ASTR + c4] = *(const float4*)&Kt[row * 64 + c4];
            *(float4*)&Vs[row * ASTR + c4] = *(const float4*)&Vt[row * 64 + c4];
        }
        __syncthreads();

        // S = Q K^T * scale + mask   (thread covers j = 4*jj + c)
        float s[16];
#pragma unroll
        for (int jj = 0; jj < 16; jj++) s[jj] = 0.0f;
#pragma unroll 4
        for (int d4 = 0; d4 < 16; d4++) {
            float4 qv = *(const float4*)&Qs[r * ASTR + d4 * 4];
#pragma unroll
            for (int jj = 0; jj < 16; jj++) {
                float4 kv = *(const float4*)&Ks[(4 * jj + c) * ASTR + d4 * 4];
                s[jj] += qv.x * kv.x + qv.y * kv.y + qv.z * kv.z + qv.w * kv.w;
            }
        }
        float gm = -3.402823466e38f;
#pragma unroll
        for (int jj = 0; jj < 16; jj++) {
            s[jj] = s[jj] * 0.125f + maskb[k0 + 4 * jj + c];  // 1/sqrt(64)
            gm = fmaxf(gm, s[jj]);
        }
        gm = fmaxf(gm, __shfl_xor_sync(0xffffffffu, gm, 1));
        gm = fmaxf(gm, __shfl_xor_sync(0xffffffffu, gm, 2));
        const float mnew  = fmaxf(mrow, gm);
        const float alpha = __expf(mrow - mnew);
        float ps = 0.0f;
#pragma unroll
        for (int jj = 0; jj < 16; jj++) {
            float p = __expf(s[jj] - mnew);   // -inf -> 0
            ps += p;
            Ps[r * ASTR + 4 * jj + c] = p;
        }
        ps += __shfl_xor_sync(0xffffffffu, ps, 1);
        ps += __shfl_xor_sync(0xffffffffu, ps, 2);
        lrow = lrow * alpha + ps;
        mrow = mnew;
#pragma unroll
        for (int i = 0; i < 16; i++) O[i] *= alpha;
        __syncthreads();   // full P row visible

        // O += P @ V   (thread covers d = 16*i + 4*c + w)
#pragma unroll 4
        for (int j4 = 0; j4 < 16; j4++) {
            float4 p4 = *(const float4*)&Ps[r * ASTR + j4 * 4];
            float pu[4] = {p4.x, p4.y, p4.z, p4.w};
#pragma unroll
            for (int u = 0; u < 4; u++) {
                const float* vrow = &Vs[(j4 * 4 + u) * ASTR + 4 * c];
                const float pj = pu[u];
                float4 v0 = *(const float4*)&vrow[0];
                float4 v1 = *(const float4*)&vrow[16];
                float4 v2 = *(const float4*)&vrow[32];
                float4 v3 = *(const float4*)&vrow[48];
                O[0]  += pj * v0.x; O[1]  += pj * v0.y; O[2]  += pj * v0.z; O[3]  += pj * v0.w;
                O[4]  += pj * v1.x; O[5]  += pj * v1.y; O[6]  += pj * v1.z; O[7]  += pj * v1.w;
                O[8]  += pj * v2.x; O[9]  += pj * v2.y; O[10] += pj * v2.z; O[11] += pj * v2.w;
                O[12] += pj * v3.x; O[13] += pj * v3.y; O[14] += pj * v3.z; O[15] += pj * v3.w;
            }
        }
    }

    const float inv = 1.0f / lrow;
    float* outp = &g_attn[((size_t)(b * SEQ + q0 + r)) * EMB + h * HD + 4 * c];
#pragma unroll
    for (int i = 0; i < 4; i++) {
        float4 o4 = make_float4(O[4 * i] * inv, O[4 * i + 1] * inv,
                                O[4 * i + 2] * inv, O[4 * i + 3] * inv);
        *(float4*)&outp[16 * i] = o4;
    }
}

// ---------------- launch -----------------------------------------------------
extern "C" void kernel_launch(void* const* d_in, const int* in_sizes, int n_in,
                              void* d_out, int out_size)
{
    const float* q    = (const float*)d_in[0];
    const float* k    = (const float*)d_in[1];
    const float* v    = (const float*)d_in[2];
    const void*  mask = d_in[3];
    const float* Wq   = (const float*)d_in[4];
    const float* bq   = (const float*)d_in[5];
    const float* Wk   = (const float*)d_in[6];
    const float* bk   = (const float*)d_in[7];
    const float* Wv   = (const float*)d_in[8];
    const float* bv   = (const float*)d_in[9];
    const float* Wo   = (const float*)d_in[10];
    const float* bo   = (const float*)d_in[11];
    float* out = (float*)d_out;

    float *pQ, *pK, *pV, *pA;
    cudaGetSymbolAddress((void**)&pQ, g_Qp);
    cudaGetSymbolAddress((void**)&pK, g_Kp);
    cudaGetSymbolAddress((void**)&pV, g_Vp);
    cudaGetSymbolAddress((void**)&pA, g_attn);

    cudaFuncSetAttribute(attn_kernel,
                         cudaFuncAttributeMaxDynamicSharedMemorySize, ATTN_SMEM);

    prep_mask_kernel<<<1, 1024>>>(mask);

    const dim3 ggrid(EMB / GBN, MROWS / GBM);   // (8, 32)
    gemm_nt_kernel<<<ggrid, 256>>>(q, Wq, bq, pQ, MROWS, EMB, EMB, 1);
    gemm_nt_kernel<<<ggrid, 256>>>(k, Wk, bk, pK, MROWS, EMB, EMB, 1);
    gemm_nt_kernel<<<ggrid, 256>>>(v, Wv, bv, pV, MROWS, EMB, EMB, 1);

    attn_kernel<<<dim3(SEQ / 64, NH, BATCH), 256, ATTN_SMEM>>>();

    gemm_nt_kernel<<<ggrid, 256>>>(pA, Wo, bo, out, MROWS, EMB, EMB, 0);
}

// round 5
// speedup vs baseline: 1.6829x; 1.6829x over previous
#include <cuda_runtime.h>
#include <math.h>

#define BATCH 2
#define SEQ   2048
#define EMB   1024
#define NH    16
#define HD    64
#define MROWS (BATCH * SEQ)   // 4096

// ---------------- scratch (device globals; no allocations allowed) ----------
__device__ float g_Qp[(size_t)BATCH * NH * SEQ * HD];   // [B,H,S,D]
__device__ float g_Kp[(size_t)BATCH * NH * SEQ * HD];
__device__ float g_Vp[(size_t)BATCH * NH * SEQ * HD];
__device__ float g_attn[(size_t)BATCH * SEQ * EMB];     // [B,S,E] pre-out-proj
__device__ float g_maskf[BATCH * SEQ];                  // additive mask (-inf / 0)

// ---------------- helpers ----------------------------------------------------
__device__ __forceinline__ unsigned f2tf(float x) {
    unsigned r; asm("cvt.rna.tf32.f32 %0, %1;" : "=r"(r) : "f"(x)); return r;
}

// D += A*B, m16n8k8 tf32. A row-major 16x8, B col-major 8x8.
// a0:(r,c) a1:(r+8,c) a2:(r,c+4) a3:(r+8,c+4)  r=lane>>2, c=lane&3
// b0:(k=lane&3, n=lane>>2) b1:(k+4, n)
// d0:(r,2c) d1:(r,2c+1) d2:(r+8,2c) d3:(r+8,2c+1)
__device__ __forceinline__ void mma_tf32(float d[4], const uint4& a,
                                         unsigned b0, unsigned b1) {
    asm volatile("mma.sync.aligned.m16n8k8.row.col.f32.tf32.tf32.f32 "
        "{%0,%1,%2,%3}, {%4,%5,%6,%7}, {%8,%9}, {%0,%1,%2,%3};"
        : "+f"(d[0]), "+f"(d[1]), "+f"(d[2]), "+f"(d[3])
        : "r"(a.x), "r"(a.y), "r"(a.z), "r"(a.w), "r"(b0), "r"(b1));
}

// fragment-layout smem index helpers
// A-side: [kstep][mtile][lane][reg]  reg = (row>>3)&1 | ((k>>2)&1)<<1
// B-side: [kstep][npair][lane][pos]  pos = (k>>2)&1  | (atom&1)<<1
__device__ __forceinline__ int afrag_idx(int ntiles, int kstep, int mtile,
                                         int row, int k) {
    return (((kstep)*ntiles + mtile)*32 + (((row&7)<<2)|(k&3)))*4
         + (((row>>3)&1) | (((k>>2)&1)<<1));
}
__device__ __forceinline__ int bfrag_idx(int npairs, int kstep, int n, int k) {
    int nt = n >> 3;
    return (((kstep)*npairs + (nt>>1))*32 + (((n&7)<<2)|(k&3)))*4
         + (((k>>2)&1) | ((nt&1)<<1));
}

// ---------------- mask canonicalization -------------------------------------
__global__ void prep_mask_kernel(const void* __restrict__ raw) {
    __shared__ int s_not01, s_notf;
    const int t = threadIdx.x;
    if (t == 0) { s_not01 = 0; s_notf = 0; }
    __syncthreads();
    const unsigned int* w = (const unsigned int*)raw;
    for (int i = t; i < (BATCH * SEQ) / 4; i += blockDim.x) {
        unsigned int v = w[i];
        if (v != 0u && v != 1u)          s_not01 = 1;
        if (v != 0u && v != 0x3F800000u) s_notf  = 1;
    }
    __syncthreads();
    const int mode = s_not01 ? (s_notf ? 0 : 2) : 1;  // 0=u8 1=i32 2=f32
    for (int i = t; i < BATCH * SEQ; i += blockDim.x) {
        bool mset;
        if (mode == 1)      mset = ((const int*)raw)[i] != 0;
        else if (mode == 2) mset = ((const float*)raw)[i] != 0.0f;
        else                mset = ((const unsigned char*)raw)[i] != 0;
        g_maskf[i] = mset ? -INFINITY : 0.0f;
    }
}

// ---------------- TF32 GEMM: C = A @ B^T + bias ------------------------------
// A [M,K] rm, B [N,K] rm. 128x128 block tile, k-tile 32, 8 warps.
// Warp tile 32(m) x 64(n): 2 m-atoms x 8 n-atoms of m16n8k8.
__global__ __launch_bounds__(256, 2)
void gemm_tf32_kernel(const float* __restrict__ A, const float* __restrict__ B,
                      const float* __restrict__ bias, float* __restrict__ C,
                      int M, int N, int K, int out_mode)
{
    __shared__ __align__(16) unsigned Af[4096];  // [4][8][32][4]
    __shared__ __align__(16) unsigned Bf[4096];  // [4][8][32][4]

    const int bm = blockIdx.y * 128, bn = blockIdx.x * 128;
    const int tid = threadIdx.x, lane = tid & 31, warp = tid >> 5;
    const int wm = warp >> 1, wn = warp & 1;   // 4x2 warp grid

    float acc[2][8][4];
#pragma unroll
    for (int i = 0; i < 2; i++)
#pragma unroll
        for (int j = 0; j < 8; j++)
#pragma unroll
            for (int e = 0; e < 4; e++) acc[i][j][e] = 0.0f;

    const int lrow = tid >> 1, lkh = (tid & 1) * 16;
    for (int k0 = 0; k0 < K; k0 += 32) {
        __syncthreads();
        {
            const float* ap = &A[(size_t)(bm + lrow) * K + k0 + lkh];
            const float* bp = &B[(size_t)(bn + lrow) * K + k0 + lkh];
#pragma unroll
            for (int q = 0; q < 4; q++) {
                float4 va = *(const float4*)(ap + q * 4);
                float4 vb = *(const float4*)(bp + q * 4);
                float aa[4] = {va.x, va.y, va.z, va.w};
                float bb[4] = {vb.x, vb.y, vb.z, vb.w};
#pragma unroll
                for (int e = 0; e < 4; e++) {
                    int k = lkh + q * 4 + e;
                    Af[afrag_idx(8, k >> 3, lrow >> 4, lrow, k)] = f2tf(aa[e]);
                    Bf[bfrag_idx(8, k >> 3, lrow, k)]            = f2tf(bb[e]);
                }
            }
        }
        __syncthreads();
#pragma unroll
        for (int s = 0; s < 4; s++) {
            uint4 a[2], bq[4];
#pragma unroll
            for (int i = 0; i < 2; i++)
                a[i] = *(const uint4*)&Af[((s * 8 + 2 * wm + i) * 32 + lane) * 4];
#pragma unroll
            for (int jp = 0; jp < 4; jp++)
                bq[jp] = *(const uint4*)&Bf[((s * 8 + 4 * wn + jp) * 32 + lane) * 4];
#pragma unroll
            for (int i = 0; i < 2; i++)
#pragma unroll
                for (int jp = 0; jp < 4; jp++) {
                    mma_tf32(acc[i][2 * jp],     a[i], bq[jp].x, bq[jp].y);
                    mma_tf32(acc[i][2 * jp + 1], a[i], bq[jp].z, bq[jp].w);
                }
        }
    }

    // epilogue: atom (i,ja): rows bm+wm*32+i*16+{r,r+8}, cols bn+wn*64+ja*8+2c{,+1}
    const int r4 = lane >> 2, c2 = 2 * (lane & 3);
#pragma unroll
    for (int i = 0; i < 2; i++) {
#pragma unroll
        for (int ja = 0; ja < 8; ja++) {
            const int row0 = bm + wm * 32 + i * 16 + r4;
            const int col  = bn + wn * 64 + ja * 8 + c2;
            const float bv0 = bias[col], bv1 = bias[col + 1];
#pragma unroll
            for (int hf = 0; hf < 2; hf++) {
                const int row = row0 + 8 * hf;
                float2 v = make_float2(acc[i][ja][2 * hf] + bv0,
                                       acc[i][ja][2 * hf + 1] + bv1);
                if (out_mode == 0) {
                    *(float2*)&C[(size_t)row * N + col] = v;
                } else {
                    const int hh = col >> 6, d = col & (HD - 1);
                    const int bi = row >> 11, sq = row & (SEQ - 1);
                    *(float2*)&C[(((size_t)(bi * NH + hh)) * SEQ + sq) * HD + d] = v;
                }
            }
        }
    }
}

// ---------------- TF32 flash attention ---------------------------------------
// Block = (b, h, 128-row q tile), 256 threads = 8 warps. Warp w owns q rows
// 16w..16w+15. k-tile 64 keys. All MMAs m16n8k8 tf32, fp32 online softmax.
#define ATT_SMEM ((8192 + 4096 + 4096 + 8192) * 4 + 2048 * 4)  // 106496 B

__global__ __launch_bounds__(256, 2)
void attn_tf32_kernel()
{
    extern __shared__ __align__(16) unsigned smu[];
    unsigned* Qf = smu;           // [8 kstep(d)][8 mtile][32][4]   = 8192
    unsigned* Kf = Qf + 8192;     // [8 kstep(d)][4 npair(j)][32][4]= 4096
    unsigned* Vf = Kf + 4096;     // [8 kstep(j)][4 npair(d)][32][4]= 4096
    unsigned* Ps = Vf + 4096;     // per-warp [8 kstep(j)][32][4]   = 8192
    float*    Ms = (float*)(Ps + 8192);  // 2048

    const int b  = blockIdx.z;
    const int h  = blockIdx.y;
    const int q0 = blockIdx.x * 128;
    const int tid = threadIdx.x, lane = tid & 31, w = tid >> 5;
    const int r4 = lane >> 2, c2 = 2 * (lane & 3);

    const float* Qg = &g_Qp[(((size_t)(b * NH + h)) * SEQ + q0) * HD];
    const float* Kg = &g_Kp[((size_t)(b * NH + h)) * SEQ * HD];
    const float* Vg = &g_Vp[((size_t)(b * NH + h)) * SEQ * HD];

    // Q -> fragment smem (scaled by 1/sqrt(64), exact pow2)
    {
        const int row = tid >> 1, dh = (tid & 1) * 32;
        const float* qp = Qg + (size_t)row * HD + dh;
#pragma unroll
        for (int q = 0; q < 8; q++) {
            float4 v = *(const float4*)(qp + q * 4);
            float vv[4] = {v.x, v.y, v.z, v.w};
#pragma unroll
            for (int e = 0; e < 4; e++) {
                int d = dh + q * 4 + e;
                Qf[afrag_idx(8, d >> 3, row >> 4, row, d)] = f2tf(vv[e] * 0.125f);
            }
        }
    }
    for (int i = tid; i < SEQ; i += 256) Ms[i] = g_maskf[b * SEQ + i];

    float Oa[8][4];
#pragma unroll
    for (int ja = 0; ja < 8; ja++)
#pragma unroll
        for (int e = 0; e < 4; e++) Oa[ja][e] = 0.0f;
    float m0 = -3.402823466e38f, m1 = -3.402823466e38f;
    float l0 = 0.0f, l1 = 0.0f;

    const int lj = tid >> 2, ldh = (tid & 3) * 16;   // loader coords

    for (int kt = 0; kt < SEQ / 64; kt++) {
        const int k0 = kt * 64;
        __syncthreads();
        {   // K,V tiles -> fragment smem
            const float* kp = Kg + (size_t)(k0 + lj) * HD + ldh;
            const float* vp = Vg + (size_t)(k0 + lj) * HD + ldh;
#pragma unroll
            for (int q = 0; q < 4; q++) {
                float4 kv = *(const float4*)(kp + q * 4);
                float4 vv = *(const float4*)(vp + q * 4);
                float ka[4] = {kv.x, kv.y, kv.z, kv.w};
                float va[4] = {vv.x, vv.y, vv.z, vv.w};
#pragma unroll
                for (int e = 0; e < 4; e++) {
                    int d = ldh + q * 4 + e;
                    // K: n=key j, k=d
                    Kf[bfrag_idx(4, d >> 3, lj, d)] = f2tf(ka[e]);
                    // V: n=d, k=key j
                    Vf[bfrag_idx(4, lj >> 3, d, lj)] = f2tf(va[e]);
                }
            }
        }
        __syncthreads();

        // S = (Q/8) K^T : warp strip 16 x 64
        float s[8][4];
#pragma unroll
        for (int ja = 0; ja < 8; ja++)
#pragma unroll
            for (int e = 0; e < 4; e++) s[ja][e] = 0.0f;
#pragma unroll
        for (int s8 = 0; s8 < 8; s8++) {
            uint4 a = *(const uint4*)&Qf[((s8 * 8 + w) * 32 + lane) * 4];
#pragma unroll
            for (int jp = 0; jp < 4; jp++) {
                uint4 bq = *(const uint4*)&Kf[((s8 * 4 + jp) * 32 + lane) * 4];
                mma_tf32(s[2 * jp],     a, bq.x, bq.y);
                mma_tf32(s[2 * jp + 1], a, bq.z, bq.w);
            }
        }

        // mask + online softmax (rows r4 and r4+8)
        float mx0 = -3.402823466e38f, mx1 = -3.402823466e38f;
#pragma unroll
        for (int ja = 0; ja < 8; ja++) {
            float2 mv = *(const float2*)&Ms[k0 + 8 * ja + c2];
            s[ja][0] += mv.x; s[ja][1] += mv.y;
            s[ja][2] += mv.x; s[ja][3] += mv.y;
            mx0 = fmaxf(mx0, fmaxf(s[ja][0], s[ja][1]));
            mx1 = fmaxf(mx1, fmaxf(s[ja][2], s[ja][3]));
        }
        mx0 = fmaxf(mx0, __shfl_xor_sync(0xffffffffu, mx0, 1));
        mx0 = fmaxf(mx0, __shfl_xor_sync(0xffffffffu, mx0, 2));
        mx1 = fmaxf(mx1, __shfl_xor_sync(0xffffffffu, mx1, 1));
        mx1 = fmaxf(mx1, __shfl_xor_sync(0xffffffffu, mx1, 2));
        const float mn0 = fmaxf(m0, mx0), mn1 = fmaxf(m1, mx1);
        const float al0 = __expf(m0 - mn0), al1 = __expf(m1 - mn1);
        float rs0 = 0.0f, rs1 = 0.0f;
        unsigned* Pw = Ps + w * 1024;
#pragma unroll
        for (int ja = 0; ja < 8; ja++) {
            s[ja][0] = __expf(s[ja][0] - mn0);
            s[ja][1] = __expf(s[ja][1] - mn0);
            s[ja][2] = __expf(s[ja][2] - mn1);
            s[ja][3] = __expf(s[ja][3] - mn1);
            rs0 += s[ja][0] + s[ja][1];
            rs1 += s[ja][2] + s[ja][3];
            // C-frag -> A-frag layout conversion (warp-private)
#pragma unroll
            for (int hf = 0; hf < 2; hf++)
#pragma unroll
                for (int e = 0; e < 2; e++) {
                    int k = 8 * ja + c2 + e;
                    int al = (r4 << 2) | (k & 3);
                    int pos = hf | (((k >> 2) & 1) << 1);
                    Pw[(ja * 32 + al) * 4 + pos] = f2tf(s[ja][2 * hf + e]);
                }
        }
        rs0 += __shfl_xor_sync(0xffffffffu, rs0, 1);
        rs0 += __shfl_xor_sync(0xffffffffu, rs0, 2);
        rs1 += __shfl_xor_sync(0xffffffffu, rs1, 1);
        rs1 += __shfl_xor_sync(0xffffffffu, rs1, 2);
        l0 = l0 * al0 + rs0; l1 = l1 * al1 + rs1;
        m0 = mn0; m1 = mn1;
#pragma unroll
        for (int ja = 0; ja < 8; ja++) {
            Oa[ja][0] *= al0; Oa[ja][1] *= al0;
            Oa[ja][2] *= al1; Oa[ja][3] *= al1;
        }
        __syncwarp();

        // O += P V
#pragma unroll
        for (int s8 = 0; s8 < 8; s8++) {
            uint4 a = *(const uint4*)&Pw[(s8 * 32 + lane) * 4];
#pragma unroll
            for (int dp = 0; dp < 4; dp++) {
                uint4 bq = *(const uint4*)&Vf[((s8 * 4 + dp) * 32 + lane) * 4];
                mma_tf32(Oa[2 * dp],     a, bq.x, bq.y);
                mma_tf32(Oa[2 * dp + 1], a, bq.z, bq.w);
            }
        }
    }

    const float i0 = 1.0f / l0, i1 = 1.0f / l1;
    float* op0 = &g_attn[((size_t)(b * SEQ) + q0 + 16 * w + r4) * EMB + h * HD];
    float* op1 = op0 + 8 * EMB;
#pragma unroll
    for (int ja = 0; ja < 8; ja++) {
        const int d = 8 * ja + c2;
        *(float2*)&op0[d] = make_float2(Oa[ja][0] * i0, Oa[ja][1] * i0);
        *(float2*)&op1[d] = make_float2(Oa[ja][2] * i1, Oa[ja][3] * i1);
    }
}

// ---------------- launch -----------------------------------------------------
extern "C" void kernel_launch(void* const* d_in, const int* in_sizes, int n_in,
                              void* d_out, int out_size)
{
    const float* q    = (const float*)d_in[0];
    const float* k    = (const float*)d_in[1];
    const float* v    = (const float*)d_in[2];
    const void*  mask = d_in[3];
    const float* Wq   = (const float*)d_in[4];
    const float* bq   = (const float*)d_in[5];
    const float* Wk   = (const float*)d_in[6];
    const float* bk   = (const float*)d_in[7];
    const float* Wv   = (const float*)d_in[8];
    const float* bv   = (const float*)d_in[9];
    const float* Wo   = (const float*)d_in[10];
    const float* bo   = (const float*)d_in[11];
    float* out = (float*)d_out;

    float *pQ, *pK, *pV, *pA;
    cudaGetSymbolAddress((void**)&pQ, g_Qp);
    cudaGetSymbolAddress((void**)&pK, g_Kp);
    cudaGetSymbolAddress((void**)&pV, g_Vp);
    cudaGetSymbolAddress((void**)&pA, g_attn);

    cudaFuncSetAttribute(attn_tf32_kernel,
                         cudaFuncAttributeMaxDynamicSharedMemorySize, ATT_SMEM);

    prep_mask_kernel<<<1, 1024>>>(mask);

    const dim3 ggrid(EMB / 128, MROWS / 128);   // (8, 32)
    gemm_tf32_kernel<<<ggrid, 256>>>(q, Wq, bq, pQ, MROWS, EMB, EMB, 1);
    gemm_tf32_kernel<<<ggrid, 256>>>(k, Wk, bk, pK, MROWS, EMB, EMB, 1);
    gemm_tf32_kernel<<<ggrid, 256>>>(v, Wv, bv, pV, MROWS, EMB, EMB, 1);

    attn_tf32_kernel<<<dim3(SEQ / 128, NH, BATCH), 256, ATT_SMEM>>>();

    gemm_tf32_kernel<<<ggrid, 256>>>(pA, Wo, bo, out, MROWS, EMB, EMB, 0);
}

// round 6
// speedup vs baseline: 5.5832x; 3.3176x over previous
#include <cuda_runtime.h>
#include <math.h>

#define BATCH 2
#define SEQ   2048
#define EMB   1024
#define NH    16
#define HD    64
#define MROWS (BATCH * SEQ)   // 4096

// ---------------- scratch (device globals; no allocations allowed) ----------
__device__ float g_Qp[(size_t)BATCH * NH * SEQ * HD];   // [B,H,S,D] (tf32-rounded)
__device__ float g_Kp[(size_t)BATCH * NH * SEQ * HD];   // [B,H,S,D] (tf32-rounded)
__device__ float g_Vt[(size_t)BATCH * NH * HD * SEQ];   // [B,H,D,S] transposed (rounded)
__device__ float g_attn[(size_t)BATCH * SEQ * EMB];     // [B,S,E] pre-out-proj
__device__ float g_maskf[BATCH * SEQ];                  // additive mask (-inf / 0)
__device__ float g_Wr[4 * (size_t)EMB * EMB];           // tf32-rounded Wq,Wk,Wv,Wo

// ---------------- small helpers ----------------------------------------------
__device__ __forceinline__ unsigned smem_u32(const void* p) {
    unsigned a;
    asm("{ .reg .u64 t; cvta.to.shared.u64 t, %1; cvt.u32.u64 %0, t; }"
        : "=r"(a) : "l"(p));
    return a;
}
__device__ __forceinline__ void cp16(unsigned s, const void* g) {
    asm volatile("cp.async.cg.shared.global [%0], [%1], 16;" :: "r"(s), "l"(g));
}
#define CP_COMMIT() asm volatile("cp.async.commit_group;")
#define CP_WAIT(N)  asm volatile("cp.async.wait_group %0;" :: "n"(N))

__device__ __forceinline__ unsigned f2tf(float x) {
    unsigned r; asm("cvt.rna.tf32.f32 %0, %1;" : "=r"(r) : "f"(x)); return r;
}
__device__ __forceinline__ unsigned cvtu(unsigned u) {
    unsigned r; float f = __uint_as_float(u);
    asm("cvt.rna.tf32.f32 %0, %1;" : "=r"(r) : "f"(f)); return r;
}

// D += A*B, m16n8k8 tf32 (fragment layouts per PTX ISA).
__device__ __forceinline__ void mma_tf32(float d[4], const uint4& a,
                                         unsigned b0, unsigned b1) {
    asm volatile("mma.sync.aligned.m16n8k8.row.col.f32.tf32.tf32.f32 "
        "{%0,%1,%2,%3}, {%4,%5,%6,%7}, {%8,%9}, {%0,%1,%2,%3};"
        : "+f"(d[0]), "+f"(d[1]), "+f"(d[2]), "+f"(d[3])
        : "r"(a.x), "r"(a.y), "r"(a.z), "r"(a.w), "r"(b0), "r"(b1));
}

// ldmatrix.x4 over a swizzled f32 tile (row = rchunks 16B-chunks wide).
// Returns (m0,m1,m2,m3) = A-frag (a0,a1,a2,a3) for rows brow..brow+15,
// k-group s (k = 8s..8s+7); identically B-frags for two 8-wide n-atoms.
__device__ __forceinline__ uint4 ldsm4(unsigned tbase, int rchunks, int brow,
                                       int s, int lane) {
    int row   = brow + (lane & 7) + ((lane >> 3) & 1) * 8;
    int chunk = (2 * s + (lane >> 4)) ^ (lane & 7);
    unsigned addr = tbase + (unsigned)((row * rchunks + chunk) * 16);
    uint4 r;
    asm volatile("ldmatrix.sync.aligned.m8n8.x4.shared.b16 {%0,%1,%2,%3}, [%4];"
        : "=r"(r.x), "=r"(r.y), "=r"(r.z), "=r"(r.w) : "r"(addr));
    return r;
}

// ---------------- mask canonicalization -------------------------------------
__global__ void prep_mask_kernel(const void* __restrict__ raw) {
    __shared__ int s_not01, s_notf;
    const int t = threadIdx.x;
    if (t == 0) { s_not01 = 0; s_notf = 0; }
    __syncthreads();
    const unsigned int* w = (const unsigned int*)raw;
    for (int i = t; i < (BATCH * SEQ) / 4; i += blockDim.x) {
        unsigned int v = w[i];
        if (v != 0u && v != 1u)          s_not01 = 1;
        if (v != 0u && v != 0x3F800000u) s_notf  = 1;
    }
    __syncthreads();
    const int mode = s_not01 ? (s_notf ? 0 : 2) : 1;  // 0=u8 1=i32 2=f32
    for (int i = t; i < BATCH * SEQ; i += blockDim.x) {
        bool mset;
        if (mode == 1)      mset = ((const int*)raw)[i] != 0;
        else if (mode == 2) mset = ((const float*)raw)[i] != 0.0f;
        else                mset = ((const unsigned char*)raw)[i] != 0;
        g_maskf[i] = mset ? -INFINITY : 0.0f;
    }
}

// ---------------- weight pre-rounding ----------------------------------------
__global__ void prep_weights_kernel(const float* __restrict__ Wq,
                                    const float* __restrict__ Wk,
                                    const float* __restrict__ Wv,
                                    const float* __restrict__ Wo) {
    const size_t n = (size_t)EMB * EMB;                 // 2^20
    const size_t stride = (size_t)gridDim.x * blockDim.x;
    for (size_t i = (size_t)blockIdx.x * blockDim.x + threadIdx.x;
         i < 4 * n; i += stride) {
        int m = (int)(i >> 20);
        size_t off = i & (n - 1);
        const float* src = m == 0 ? Wq : (m == 1 ? Wk : (m == 2 ? Wv : Wo));
        g_Wr[i] = __uint_as_float(f2tf(src[off]));
    }
}

// ---------------- TF32 GEMM body: C = A @ W^T + bias -------------------------
// 128x128 tile, BK=32, cp.async double-buffered, ldmatrix fragments.
// mode 0: plain row-major. mode 1: [B,H,S,D] rounded. mode 2: [B,H,D,S] rounded.
#define GEMM_SMEM 65536

__device__ __forceinline__ void gemm_body(const float* __restrict__ A,
                                          const float* __restrict__ W,
                                          const float* __restrict__ bias,
                                          float* __restrict__ C, int mode)
{
    extern __shared__ char smg[];
    const unsigned sb = smem_u32(smg);
    const int bm = blockIdx.y * 128, bn = blockIdx.x * 128;
    const int tid = threadIdx.x, lane = tid & 31, warp = tid >> 5;
    const int wm = warp >> 1, wn = warp & 1;           // 4x2 warp grid

    float acc[2][8][4];
#pragma unroll
    for (int i = 0; i < 2; i++)
#pragma unroll
        for (int j = 0; j < 8; j++)
#pragma unroll
            for (int e = 0; e < 4; e++) acc[i][j][e] = 0.0f;

    auto issue = [&](int t) {
        const unsigned As = sb + (t & 1) * 16384;
        const unsigned Bs = sb + 32768 + (t & 1) * 16384;
        const int k0 = t * 32;
#pragma unroll
        for (int p = 0; p < 4; p++) {
            int idx = tid + p * 256;
            int row = idx >> 3, c = idx & 7, pc = c ^ (row & 7);
            cp16(As + (row * 8 + pc) * 16, A + (size_t)(bm + row) * EMB + k0 + c * 4);
            cp16(Bs + (row * 8 + pc) * 16, W + (size_t)(bn + row) * EMB + k0 + c * 4);
        }
        CP_COMMIT();
    };

    issue(0);
    for (int t = 0; t < 32; t++) {
        if (t < 31) { issue(t + 1); CP_WAIT(1); }
        else        { CP_WAIT(0); }
        __syncthreads();
        const unsigned Ab = sb + (t & 1) * 16384;
        const unsigned Bb = sb + 32768 + (t & 1) * 16384;
#pragma unroll
        for (int s = 0; s < 4; s++) {
            uint4 a0 = ldsm4(Ab, 8, wm * 32, s, lane);
            uint4 a1 = ldsm4(Ab, 8, wm * 32 + 16, s, lane);
            a0.x = cvtu(a0.x); a0.y = cvtu(a0.y); a0.z = cvtu(a0.z); a0.w = cvtu(a0.w);
            a1.x = cvtu(a1.x); a1.y = cvtu(a1.y); a1.z = cvtu(a1.z); a1.w = cvtu(a1.w);
#pragma unroll
            for (int jp = 0; jp < 4; jp++) {
                uint4 b = ldsm4(Bb, 8, wn * 64 + jp * 16, s, lane);
                mma_tf32(acc[0][2 * jp],     a0, b.x, b.z);
                mma_tf32(acc[0][2 * jp + 1], a0, b.y, b.w);
                mma_tf32(acc[1][2 * jp],     a1, b.x, b.z);
                mma_tf32(acc[1][2 * jp + 1], a1, b.y, b.w);
            }
        }
        __syncthreads();
    }

    const int r4 = lane >> 2, c2 = 2 * (lane & 3);
#pragma unroll
    for (int i = 0; i < 2; i++) {
#pragma unroll
        for (int ja = 0; ja < 8; ja++) {
            const int row0 = bm + wm * 32 + i * 16 + r4;
            const int col  = bn + wn * 64 + ja * 8 + c2;
            const float b0v = bias[col], b1v = bias[col + 1];
#pragma unroll
            for (int hf = 0; hf < 2; hf++) {
                const int row = row0 + 8 * hf;
                float v0 = acc[i][ja][2 * hf]     + b0v;
                float v1 = acc[i][ja][2 * hf + 1] + b1v;
                if (mode == 0) {
                    *(float2*)&C[(size_t)row * EMB + col] = make_float2(v0, v1);
                } else {
                    v0 = __uint_as_float(f2tf(v0));
                    v1 = __uint_as_float(f2tf(v1));
                    const int hh = col >> 6, d = col & (HD - 1);
                    const int bi = row >> 11, sq = row & (SEQ - 1);
                    if (mode == 1) {
                        *(float2*)&C[(((size_t)(bi * NH + hh)) * SEQ + sq) * HD + d]
                            = make_float2(v0, v1);
                    } else {  // transposed [B,H,D,S]
                        float* p = &C[((size_t)(bi * NH + hh) * HD + d) * SEQ + sq];
                        p[0]   = v0;
                        p[SEQ] = v1;   // d+1 row
                    }
                }
            }
        }
    }
}

__global__ __launch_bounds__(256, 2)
void gemm_qkv_kernel(const float* __restrict__ q, const float* __restrict__ k,
                     const float* __restrict__ v, const float* __restrict__ bq,
                     const float* __restrict__ bk, const float* __restrict__ bv)
{
    const int z = blockIdx.z;
    const float* A    = z == 0 ? q  : (z == 1 ? k  : v);
    const float* bias = z == 0 ? bq : (z == 1 ? bk : bv);
    const float* W    = g_Wr + (size_t)z * EMB * EMB;
    float* C          = z == 0 ? g_Qp : (z == 1 ? g_Kp : g_Vt);
    gemm_body(A, W, bias, C, z == 2 ? 2 : 1);
}

__global__ __launch_bounds__(256, 2)
void gemm_out_kernel(const float* __restrict__ bo, float* __restrict__ out)
{
    gemm_body(g_attn, g_Wr + (size_t)3 * EMB * EMB, bo, out, 0);
}

// ---------------- TF32 flash attention ---------------------------------------
// Block = (b, h, 128 q-rows), 256 thr = 8 warps; warp w owns q rows 16w..16w+15.
// K-tile 64 keys, cp.async double-buffered. Q frags live in registers.
// smem: Qs 32KB | K[2] 32KB | Vt[2] 32KB | mask 8KB = 106496 B
#define ATT_SMEM 106496

__global__ __launch_bounds__(256, 2)
void attn_kernel()
{
    extern __shared__ char sma[];
    const unsigned sb  = smem_u32(sma);
    const unsigned Qsb = sb;
    const unsigned Ksb = sb + 32768;
    const unsigned Vsb = sb + 65536;
    float* Ms = (float*)(sma + 98304);

    const int b  = blockIdx.z;
    const int h  = blockIdx.y;
    const int q0 = blockIdx.x * 128;
    const int tid = threadIdx.x, lane = tid & 31, w = tid >> 5;
    const int r4 = lane >> 2, c2 = 2 * (lane & 3);

    const float* Qg = g_Qp + ((size_t)(b * NH + h) * SEQ + q0) * HD;
    const float* Kg = g_Kp + (size_t)(b * NH + h) * SEQ * HD;
    const float* Vg = g_Vt + (size_t)(b * NH + h) * HD * SEQ;

    // async-load Q tile (128 x 64 f32)
#pragma unroll
    for (int p = 0; p < 8; p++) {
        int idx = tid + p * 256;
        int row = idx >> 4, c = idx & 15, pc = c ^ (row & 7);
        cp16(Qsb + (row * 16 + pc) * 16, Qg + (size_t)row * HD + c * 4);
    }
    CP_COMMIT();

    auto issueKV = [&](int t) {
        const unsigned Kb = Ksb + (t & 1) * 16384;
        const unsigned Vb = Vsb + (t & 1) * 16384;
        const int k0 = t * 64;
#pragma unroll
        for (int p = 0; p < 4; p++) {
            int idx = tid + p * 256;
            int row = idx >> 4, c = idx & 15, pc = c ^ (row & 7);
            cp16(Kb + (row * 16 + pc) * 16, Kg + (size_t)(k0 + row) * HD + c * 4);
            cp16(Vb + (row * 16 + pc) * 16, Vg + (size_t)row * SEQ + k0 + c * 4);
        }
        CP_COMMIT();
    };
    issueKV(0);

    for (int i = tid; i < 512; i += 256)
        ((float4*)Ms)[i] = ((const float4*)(g_maskf + b * SEQ))[i];

    CP_WAIT(1);            // Q done (KV0 may still be in flight)
    __syncthreads();

    uint4 Qf[8];
#pragma unroll
    for (int s8 = 0; s8 < 8; s8++) {
        uint4 a = ldsm4(Qsb, 16, 16 * w, s8, lane);
        a.x = __float_as_uint(__uint_as_float(a.x) * 0.125f);
        a.y = __float_as_uint(__uint_as_float(a.y) * 0.125f);
        a.z = __float_as_uint(__uint_as_float(a.z) * 0.125f);
        a.w = __float_as_uint(__uint_as_float(a.w) * 0.125f);
        Qf[s8] = a;
    }

    float Oa[8][4];
#pragma unroll
    for (int ja = 0; ja < 8; ja++)
#pragma unroll
        for (int e = 0; e < 4; e++) Oa[ja][e] = 0.0f;
    float m0 = -3.402823466e38f, m1 = -3.402823466e38f;
    float l0 = 0.0f, l1 = 0.0f;

    const int baseL = lane & ~3, cL = lane & 3;
    const int src1 = baseL | (cL >> 1);
    const int src2 = src1 | 2;
    const bool odd = cL & 1;

    for (int t = 0; t < 32; t++) {
        if (t < 31) { issueKV(t + 1); CP_WAIT(1); }
        else        { CP_WAIT(0); }
        __syncthreads();
        const unsigned Kb = Ksb + (t & 1) * 16384;
        const unsigned Vb = Vsb + (t & 1) * 16384;

        // S = (Q/8) K^T : warp strip 16 x 64
        float s[8][4];
#pragma unroll
        for (int ja = 0; ja < 8; ja++)
#pragma unroll
            for (int e = 0; e < 4; e++) s[ja][e] = 0.0f;
#pragma unroll
        for (int s8 = 0; s8 < 8; s8++) {
#pragma unroll
            for (int jp = 0; jp < 4; jp++) {
                uint4 bq = ldsm4(Kb, 16, jp * 16, s8, lane);
                mma_tf32(s[2 * jp],     Qf[s8], bq.x, bq.z);
                mma_tf32(s[2 * jp + 1], Qf[s8], bq.y, bq.w);
            }
        }

        // mask + online softmax (rows r4, r4+8)
        float mx0 = -3.402823466e38f, mx1 = -3.402823466e38f;
#pragma unroll
        for (int ja = 0; ja < 8; ja++) {
            float2 mv = *(const float2*)&Ms[t * 64 + 8 * ja + c2];
            s[ja][0] += mv.x; s[ja][1] += mv.y;
            s[ja][2] += mv.x; s[ja][3] += mv.y;
            mx0 = fmaxf(mx0, fmaxf(s[ja][0], s[ja][1]));
            mx1 = fmaxf(mx1, fmaxf(s[ja][2], s[ja][3]));
        }
        mx0 = fmaxf(mx0, __shfl_xor_sync(0xffffffffu, mx0, 1));
        mx0 = fmaxf(mx0, __shfl_xor_sync(0xffffffffu, mx0, 2));
        mx1 = fmaxf(mx1, __shfl_xor_sync(0xffffffffu, mx1, 1));
        mx1 = fmaxf(mx1, __shfl_xor_sync(0xffffffffu, mx1, 2));
        const float mn0 = fmaxf(m0, mx0), mn1 = fmaxf(m1, mx1);
        const float al0 = __expf(m0 - mn0), al1 = __expf(m1 - mn1);
        float rs0 = 0.0f, rs1 = 0.0f;
#pragma unroll
        for (int ja = 0; ja < 8; ja++) {
            s[ja][0] = __expf(s[ja][0] - mn0);
            s[ja][1] = __expf(s[ja][1] - mn0);
            s[ja][2] = __expf(s[ja][2] - mn1);
            s[ja][3] = __expf(s[ja][3] - mn1);
            rs0 += s[ja][0] + s[ja][1];
            rs1 += s[ja][2] + s[ja][3];
        }
        rs0 += __shfl_xor_sync(0xffffffffu, rs0, 1);
        rs0 += __shfl_xor_sync(0xffffffffu, rs0, 2);
        rs1 += __shfl_xor_sync(0xffffffffu, rs1, 1);
        rs1 += __shfl_xor_sync(0xffffffffu, rs1, 2);
        l0 = l0 * al0 + rs0; l1 = l1 * al1 + rs1;
        m0 = mn0; m1 = mn1;
#pragma unroll
        for (int ja = 0; ja < 8; ja++) {
            Oa[ja][0] *= al0; Oa[ja][1] *= al0;
            Oa[ja][2] *= al1; Oa[ja][3] *= al1;
        }

        // O += P V  (P C-frag -> A-frag via shuffles; V^T tiles in smem)
#pragma unroll
        for (int s8 = 0; s8 < 8; s8++) {
            float t0a = __shfl_sync(0xffffffffu, s[s8][0], src1);
            float t1a = __shfl_sync(0xffffffffu, s[s8][1], src1);
            float t2a = __shfl_sync(0xffffffffu, s[s8][2], src1);
            float t3a = __shfl_sync(0xffffffffu, s[s8][3], src1);
            float t0b = __shfl_sync(0xffffffffu, s[s8][0], src2);
            float t1b = __shfl_sync(0xffffffffu, s[s8][1], src2);
            float t2b = __shfl_sync(0xffffffffu, s[s8][2], src2);
            float t3b = __shfl_sync(0xffffffffu, s[s8][3], src2);
            uint4 pa;
            pa.x = f2tf(odd ? t1a : t0a);   // P(r4,    8*s8+cL)
            pa.y = f2tf(odd ? t3a : t2a);   // P(r4+8,  8*s8+cL)
            pa.z = f2tf(odd ? t1b : t0b);   // P(r4,    8*s8+cL+4)
            pa.w = f2tf(odd ? t3b : t2b);   // P(r4+8,  8*s8+cL+4)
#pragma unroll
            for (int dp = 0; dp < 4; dp++) {
                uint4 bq = ldsm4(Vb, 16, dp * 16, s8, lane);
                mma_tf32(Oa[2 * dp],     pa, bq.x, bq.z);
                mma_tf32(Oa[2 * dp + 1], pa, bq.y, bq.w);
            }
        }
        __syncthreads();
    }

    const float i0 = 1.0f / l0, i1 = 1.0f / l1;
    float* op0 = g_attn + ((size_t)(b * SEQ) + q0 + 16 * w + r4) * EMB + h * HD;
    float* op1 = op0 + (size_t)8 * EMB;
#pragma unroll
    for (int ja = 0; ja < 8; ja++) {
        const int d = 8 * ja + c2;
        *(float2*)&op0[d] = make_float2(Oa[ja][0] * i0, Oa[ja][1] * i0);
        *(float2*)&op1[d] = make_float2(Oa[ja][2] * i1, Oa[ja][3] * i1);
    }
}

// ---------------- launch -----------------------------------------------------
extern "C" void kernel_launch(void* const* d_in, const int* in_sizes, int n_in,
                              void* d_out, int out_size)
{
    const float* q    = (const float*)d_in[0];
    const float* k    = (const float*)d_in[1];
    const float* v    = (const float*)d_in[2];
    const void*  mask = d_in[3];
    const float* Wq   = (const float*)d_in[4];
    const float* bq   = (const float*)d_in[5];
    const float* Wk   = (const float*)d_in[6];
    const float* bk   = (const float*)d_in[7];
    const float* Wv   = (const float*)d_in[8];
    const float* bv   = (const float*)d_in[9];
    const float* Wo   = (const float*)d_in[10];
    const float* bo   = (const float*)d_in[11];
    float* out = (float*)d_out;

    cudaFuncSetAttribute(gemm_qkv_kernel,
                         cudaFuncAttributeMaxDynamicSharedMemorySize, GEMM_SMEM);
    cudaFuncSetAttribute(gemm_out_kernel,
                         cudaFuncAttributeMaxDynamicSharedMemorySize, GEMM_SMEM);
    cudaFuncSetAttribute(attn_kernel,
                         cudaFuncAttributeMaxDynamicSharedMemorySize, ATT_SMEM);

    prep_mask_kernel<<<1, 1024>>>(mask);
    prep_weights_kernel<<<512, 256>>>(Wq, Wk, Wv, Wo);

    gemm_qkv_kernel<<<dim3(8, 32, 3), 256, GEMM_SMEM>>>(q, k, v, bq, bk, bv);

    attn_kernel<<<dim3(SEQ / 128, NH, BATCH), 256, ATT_SMEM>>>();

    gemm_out_kernel<<<dim3(8, 32, 1), 256, GEMM_SMEM>>>(bo, out);
}

// round 7
// speedup vs baseline: 5.7108x; 1.0229x over previous
#include <cuda_runtime.h>
#include <math.h>

#define BATCH 2
#define SEQ   2048
#define EMB   1024
#define NH    16
#define HD    64
#define MROWS (BATCH * SEQ)   // 4096

// ---------------- scratch (device globals; no allocations allowed) ----------
__device__ float g_Qp[(size_t)BATCH * NH * SEQ * HD];   // [B,H,S,D] (tf32-rounded)
__device__ float g_Kp[(size_t)BATCH * NH * SEQ * HD];   // [B,H,S,D] (tf32-rounded)
__device__ float g_Vt[(size_t)BATCH * NH * HD * SEQ];   // [B,H,D,S] transposed (rounded)
__device__ float g_attn[(size_t)BATCH * SEQ * EMB];     // [B,S,E] (tf32-rounded)
__device__ float g_maskf[BATCH * SEQ];                  // additive mask (-inf / 0)
__device__ float g_Wr[4 * (size_t)EMB * EMB];           // tf32-rounded Wq,Wk,Wv,Wo

// ---------------- small helpers ----------------------------------------------
__device__ __forceinline__ unsigned smem_u32(const void* p) {
    unsigned a;
    asm("{ .reg .u64 t; cvta.to.shared.u64 t, %1; cvt.u32.u64 %0, t; }"
        : "=r"(a) : "l"(p));
    return a;
}
__device__ __forceinline__ void cp16(unsigned s, const void* g) {
    asm volatile("cp.async.cg.shared.global [%0], [%1], 16;" :: "r"(s), "l"(g));
}
#define CP_COMMIT() asm volatile("cp.async.commit_group;")
#define CP_WAIT(N)  asm volatile("cp.async.wait_group %0;" :: "n"(N))

__device__ __forceinline__ unsigned f2tf(float x) {
    unsigned r; asm("cvt.rna.tf32.f32 %0, %1;" : "=r"(r) : "f"(x)); return r;
}
__device__ __forceinline__ unsigned cvtu(unsigned u) {
    unsigned r; float f = __uint_as_float(u);
    asm("cvt.rna.tf32.f32 %0, %1;" : "=r"(r) : "f"(f)); return r;
}
__device__ __forceinline__ float ex2(float x) {
    float r; asm("ex2.approx.f32 %0, %1;" : "=f"(r) : "f"(x)); return r;
}

// D += A*B, m16n8k8 tf32 (fragment layouts per PTX ISA).
__device__ __forceinline__ void mma_tf32(float d[4], const uint4& a,
                                         unsigned b0, unsigned b1) {
    asm volatile("mma.sync.aligned.m16n8k8.row.col.f32.tf32.tf32.f32 "
        "{%0,%1,%2,%3}, {%4,%5,%6,%7}, {%8,%9}, {%0,%1,%2,%3};"
        : "+f"(d[0]), "+f"(d[1]), "+f"(d[2]), "+f"(d[3])
        : "r"(a.x), "r"(a.y), "r"(a.z), "r"(a.w), "r"(b0), "r"(b1));
}

__device__ __forceinline__ uint4 ldsm_at(unsigned addr) {
    uint4 r;
    asm volatile("ldmatrix.sync.aligned.m8n8.x4.shared.b16 {%0,%1,%2,%3}, [%4];"
        : "=r"(r.x), "=r"(r.y), "=r"(r.z), "=r"(r.w) : "r"(addr));
    return r;
}

// ---------------- mask canonicalization -------------------------------------
__global__ void prep_mask_kernel(const void* __restrict__ raw) {
    __shared__ int s_not01, s_notf;
    const int t = threadIdx.x;
    if (t == 0) { s_not01 = 0; s_notf = 0; }
    __syncthreads();
    const unsigned int* w = (const unsigned int*)raw;
    for (int i = t; i < (BATCH * SEQ) / 4; i += blockDim.x) {
        unsigned int v = w[i];
        if (v != 0u && v != 1u)          s_not01 = 1;
        if (v != 0u && v != 0x3F800000u) s_notf  = 1;
    }
    __syncthreads();
    const int mode = s_not01 ? (s_notf ? 0 : 2) : 1;  // 0=u8 1=i32 2=f32
    for (int i = t; i < BATCH * SEQ; i += blockDim.x) {
        bool mset;
        if (mode == 1)      mset = ((const int*)raw)[i] != 0;
        else if (mode == 2) mset = ((const float*)raw)[i] != 0.0f;
        else                mset = ((const unsigned char*)raw)[i] != 0;
        g_maskf[i] = mset ? -INFINITY : 0.0f;
    }
}

// ---------------- weight pre-rounding ----------------------------------------
__global__ void prep_weights_kernel(const float* __restrict__ Wq,
                                    const float* __restrict__ Wk,
                                    const float* __restrict__ Wv,
                                    const float* __restrict__ Wo) {
    const size_t n = (size_t)EMB * EMB;                 // 2^20
    const size_t stride = (size_t)gridDim.x * blockDim.x;
    for (size_t i = (size_t)blockIdx.x * blockDim.x + threadIdx.x;
         i < 4 * n; i += stride) {
        int m = (int)(i >> 20);
        size_t off = i & (n - 1);
        const float* src = m == 0 ? Wq : (m == 1 ? Wk : (m == 2 ? Wv : Wo));
        g_Wr[i] = __uint_as_float(f2tf(src[off]));
    }
}

// ---------------- TF32 GEMM body: C = A @ W^T + bias -------------------------
// 128x128 tile, BK=32, cp.async double-buffered, ldmatrix fragments.
// mode 0: plain row-major. mode 1: [B,H,S,D] rounded. mode 2: [B,H,D,S] rounded.
// acvt: round A-operand fragments (needed when A is raw f32).
#define GEMM_SMEM 65536

__device__ __forceinline__ void gemm_body(const float* __restrict__ A,
                                          const float* __restrict__ W,
                                          const float* __restrict__ bias,
                                          float* __restrict__ C, int mode,
                                          bool acvt)
{
    extern __shared__ char smg[];
    const unsigned sb = smem_u32(smg);
    const int bm = blockIdx.y * 128, bn = blockIdx.x * 128;
    const int tid = threadIdx.x, lane = tid & 31, warp = tid >> 5;
    const int wm = warp >> 1, wn = warp & 1;           // 4x2 warp grid

    // hoisted ldmatrix swizzle offsets (8-chunk rows, 128B row stride)
    const int rl = (lane & 7) + ((lane >> 3) & 1) * 8;
    const int hi = lane >> 4, lo = lane & 7;
    int ofs8[4];
#pragma unroll
    for (int s = 0; s < 4; s++)
        ofs8[s] = rl * 128 + (((2 * s + hi) ^ lo) << 4);

    float acc[2][8][4];
#pragma unroll
    for (int i = 0; i < 2; i++)
#pragma unroll
        for (int j = 0; j < 8; j++)
#pragma unroll
            for (int e = 0; e < 4; e++) acc[i][j][e] = 0.0f;

    auto issue = [&](int t) {
        const unsigned As = sb + (t & 1) * 16384;
        const unsigned Bs = sb + 32768 + (t & 1) * 16384;
        const int k0 = t * 32;
#pragma unroll
        for (int p = 0; p < 4; p++) {
            int idx = tid + p * 256;
            int row = idx >> 3, c = idx & 7, pc = c ^ (row & 7);
            cp16(As + (row * 8 + pc) * 16, A + (size_t)(bm + row) * EMB + k0 + c * 4);
            cp16(Bs + (row * 8 + pc) * 16, W + (size_t)(bn + row) * EMB + k0 + c * 4);
        }
        CP_COMMIT();
    };

    issue(0);
    for (int t = 0; t < 32; t++) {
        if (t < 31) { issue(t + 1); CP_WAIT(1); }
        else        { CP_WAIT(0); }
        __syncthreads();
        const unsigned Ab = sb + (t & 1) * 16384 + wm * 4096;
        const unsigned Bb = sb + 32768 + (t & 1) * 16384 + wn * 8192;
#pragma unroll
        for (int s = 0; s < 4; s++) {
            uint4 a0 = ldsm_at(Ab + ofs8[s]);
            uint4 a1 = ldsm_at(Ab + 2048 + ofs8[s]);
            if (acvt) {
                a0.x = cvtu(a0.x); a0.y = cvtu(a0.y); a0.z = cvtu(a0.z); a0.w = cvtu(a0.w);
                a1.x = cvtu(a1.x); a1.y = cvtu(a1.y); a1.z = cvtu(a1.z); a1.w = cvtu(a1.w);
            }
#pragma unroll
            for (int jp = 0; jp < 4; jp++) {
                uint4 b = ldsm_at(Bb + jp * 2048 + ofs8[s]);
                mma_tf32(acc[0][2 * jp],     a0, b.x, b.z);
                mma_tf32(acc[0][2 * jp + 1], a0, b.y, b.w);
                mma_tf32(acc[1][2 * jp],     a1, b.x, b.z);
                mma_tf32(acc[1][2 * jp + 1], a1, b.y, b.w);
            }
        }
        __syncthreads();
    }

    const int r4 = lane >> 2, c2 = 2 * (lane & 3);
#pragma unroll
    for (int i = 0; i < 2; i++) {
#pragma unroll
        for (int ja = 0; ja < 8; ja++) {
            const int row0 = bm + wm * 32 + i * 16 + r4;
            const int col  = bn + wn * 64 + ja * 8 + c2;
            const float b0v = bias[col], b1v = bias[col + 1];
#pragma unroll
            for (int hf = 0; hf < 2; hf++) {
                const int row = row0 + 8 * hf;
                float v0 = acc[i][ja][2 * hf]     + b0v;
                float v1 = acc[i][ja][2 * hf + 1] + b1v;
                if (mode == 0) {
                    *(float2*)&C[(size_t)row * EMB + col] = make_float2(v0, v1);
                } else {
                    v0 = __uint_as_float(f2tf(v0));
                    v1 = __uint_as_float(f2tf(v1));
                    const int hh = col >> 6, d = col & (HD - 1);
                    const int bi = row >> 11, sq = row & (SEQ - 1);
                    if (mode == 1) {
                        *(float2*)&C[(((size_t)(bi * NH + hh)) * SEQ + sq) * HD + d]
                            = make_float2(v0, v1);
                    } else {  // transposed [B,H,D,S]
                        float* p = &C[((size_t)(bi * NH + hh) * HD + d) * SEQ + sq];
                        p[0]   = v0;
                        p[SEQ] = v1;   // d+1 row
                    }
                }
            }
        }
    }
}

__global__ __launch_bounds__(256, 2)
void gemm_qkv_kernel(const float* __restrict__ q, const float* __restrict__ k,
                     const float* __restrict__ v, const float* __restrict__ bq,
                     const float* __restrict__ bk, const float* __restrict__ bv)
{
    const int z = blockIdx.z;
    const float* A    = z == 0 ? q  : (z == 1 ? k  : v);
    const float* bias = z == 0 ? bq : (z == 1 ? bk : bv);
    const float* W    = g_Wr + (size_t)z * EMB * EMB;
    float* C          = z == 0 ? g_Qp : (z == 1 ? g_Kp : g_Vt);
    gemm_body(A, W, bias, C, z == 2 ? 2 : 1, true);
}

__global__ __launch_bounds__(256, 2)
void gemm_out_kernel(const float* __restrict__ bo, float* __restrict__ out)
{
    // g_attn is written tf32-rounded by attn_kernel -> no A conversion needed
    gemm_body(g_attn, g_Wr + (size_t)3 * EMB * EMB, bo, out, 0, false);
}

// ---------------- TF32 flash attention ---------------------------------------
// Block = (b, h, 128 q-rows), 256 thr = 8 warps; warp w owns q rows 16w..16w+15.
// K-tile 64 keys, cp.async double-buffered. Q frags in registers, pre-scaled by
// 0.125*log2(e) -> softmax runs in exp2 domain (bare ex2.approx).
// smem: Qs 32KB | K[2] 32KB | Vt[2] 32KB | mask 8KB = 106496 B
#define ATT_SMEM 106496

__global__ __launch_bounds__(256, 2)
void attn_kernel()
{
    extern __shared__ char sma[];
    const unsigned sb  = smem_u32(sma);
    const unsigned Qsb = sb;
    const unsigned Ksb = sb + 32768;
    const unsigned Vsb = sb + 65536;
    float* Ms = (float*)(sma + 98304);

    const int b  = blockIdx.z;
    const int h  = blockIdx.y;
    const int q0 = blockIdx.x * 128;
    const int tid = threadIdx.x, lane = tid & 31, w = tid >> 5;
    const int r4 = lane >> 2, c2 = 2 * (lane & 3);

    // hoisted ldmatrix swizzle offsets (16-chunk rows, 256B row stride)
    const int rl = (lane & 7) + ((lane >> 3) & 1) * 8;
    const int hi = lane >> 4, lo = lane & 7;
    int ofs[8];
#pragma unroll
    for (int s8 = 0; s8 < 8; s8++)
        ofs[s8] = rl * 256 + (((2 * s8 + hi) ^ lo) << 4);

    const float* Qg = g_Qp + ((size_t)(b * NH + h) * SEQ + q0) * HD;
    const float* Kg = g_Kp + (size_t)(b * NH + h) * SEQ * HD;
    const float* Vg = g_Vt + (size_t)(b * NH + h) * HD * SEQ;

    // async-load Q tile (128 x 64 f32)
#pragma unroll
    for (int p = 0; p < 8; p++) {
        int idx = tid + p * 256;
        int row = idx >> 4, c = idx & 15, pc = c ^ (row & 7);
        cp16(Qsb + (row * 16 + pc) * 16, Qg + (size_t)row * HD + c * 4);
    }
    CP_COMMIT();

    auto issueKV = [&](int t) {
        const unsigned Kb = Ksb + (t & 1) * 16384;
        const unsigned Vb = Vsb + (t & 1) * 16384;
        const int k0 = t * 64;
#pragma unroll
        for (int p = 0; p < 4; p++) {
            int idx = tid + p * 256;
            int row = idx >> 4, c = idx & 15, pc = c ^ (row & 7);
            cp16(Kb + (row * 16 + pc) * 16, Kg + (size_t)(k0 + row) * HD + c * 4);
            cp16(Vb + (row * 16 + pc) * 16, Vg + (size_t)row * SEQ + k0 + c * 4);
        }
        CP_COMMIT();
    };
    issueKV(0);

    for (int i = tid; i < 512; i += 256)
        ((float4*)Ms)[i] = ((const float4*)(g_maskf + b * SEQ))[i];

    CP_WAIT(1);            // Q done (KV0 may still be in flight)
    __syncthreads();

    // scale folds 1/sqrt(64) and log2(e): softmax in exp2 domain
    const float qscale = 0.125f * 1.44269504088896340736f;
    uint4 Qf[8];
#pragma unroll
    for (int s8 = 0; s8 < 8; s8++) {
        uint4 a = ldsm_at(Qsb + w * 4096 + ofs[s8]);
        a.x = __float_as_uint(__uint_as_float(a.x) * qscale);
        a.y = __float_as_uint(__uint_as_float(a.y) * qscale);
        a.z = __float_as_uint(__uint_as_float(a.z) * qscale);
        a.w = __float_as_uint(__uint_as_float(a.w) * qscale);
        Qf[s8] = a;
    }

    float Oa[8][4];
#pragma unroll
    for (int ja = 0; ja < 8; ja++)
#pragma unroll
        for (int e = 0; e < 4; e++) Oa[ja][e] = 0.0f;
    float m0 = -3.402823466e38f, m1 = -3.402823466e38f;
    float l0 = 0.0f, l1 = 0.0f;

    const int baseL = lane & ~3, cL = lane & 3;
    const int src1 = baseL | (cL >> 1);
    const int src2 = src1 | 2;
    const bool odd = cL & 1;

    for (int t = 0; t < 32; t++) {
        if (t < 31) { issueKV(t + 1); CP_WAIT(1); }
        else        { CP_WAIT(0); }
        __syncthreads();
        const unsigned Kb = Ksb + (t & 1) * 16384;
        const unsigned Vb = Vsb + (t & 1) * 16384;

        // S = (Q*qscale) K^T : warp strip 16 x 64 (log2-domain scores)
        float s[8][4];
#pragma unroll
        for (int ja = 0; ja < 8; ja++)
#pragma unroll
            for (int e = 0; e < 4; e++) s[ja][e] = 0.0f;
#pragma unroll
        for (int s8 = 0; s8 < 8; s8++) {
#pragma unroll
            for (int jp = 0; jp < 4; jp++) {
                uint4 bq = ldsm_at(Kb + jp * 4096 + ofs[s8]);
                mma_tf32(s[2 * jp],     Qf[s8], bq.x, bq.z);
                mma_tf32(s[2 * jp + 1], Qf[s8], bq.y, bq.w);
            }
        }

        // mask + online softmax (rows r4, r4+8), exp2 domain
        float mx0 = -3.402823466e38f, mx1 = -3.402823466e38f;
#pragma unroll
        for (int ja = 0; ja < 8; ja++) {
            float2 mv = *(const float2*)&Ms[t * 64 + 8 * ja + c2];
            s[ja][0] += mv.x; s[ja][1] += mv.y;
            s[ja][2] += mv.x; s[ja][3] += mv.y;
            mx0 = fmaxf(mx0, fmaxf(s[ja][0], s[ja][1]));
            mx1 = fmaxf(mx1, fmaxf(s[ja][2], s[ja][3]));
        }
        mx0 = fmaxf(mx0, __shfl_xor_sync(0xffffffffu, mx0, 1));
        mx0 = fmaxf(mx0, __shfl_xor_sync(0xffffffffu, mx0, 2));
        mx1 = fmaxf(mx1, __shfl_xor_sync(0xffffffffu, mx1, 1));
        mx1 = fmaxf(mx1, __shfl_xor_sync(0xffffffffu, mx1, 2));
        const float mn0 = fmaxf(m0, mx0), mn1 = fmaxf(m1, mx1);
        const float al0 = ex2(m0 - mn0), al1 = ex2(m1 - mn1);
        float rs0 = 0.0f, rs1 = 0.0f;
#pragma unroll
        for (int ja = 0; ja < 8; ja++) {
            s[ja][0] = ex2(s[ja][0] - mn0);
            s[ja][1] = ex2(s[ja][1] - mn0);
            s[ja][2] = ex2(s[ja][2] - mn1);
            s[ja][3] = ex2(s[ja][3] - mn1);
            rs0 += s[ja][0] + s[ja][1];
            rs1 += s[ja][2] + s[ja][3];
        }
        rs0 += __shfl_xor_sync(0xffffffffu, rs0, 1);
        rs0 += __shfl_xor_sync(0xffffffffu, rs0, 2);
        rs1 += __shfl_xor_sync(0xffffffffu, rs1, 1);
        rs1 += __shfl_xor_sync(0xffffffffu, rs1, 2);
        l0 = l0 * al0 + rs0; l1 = l1 * al1 + rs1;
        m0 = mn0; m1 = mn1;
#pragma unroll
        for (int ja = 0; ja < 8; ja++) {
            Oa[ja][0] *= al0; Oa[ja][1] *= al0;
            Oa[ja][2] *= al1; Oa[ja][3] *= al1;
        }

        // O += P V  (P C-frag -> A-frag via shuffles; V^T tiles in smem)
#pragma unroll
        for (int s8 = 0; s8 < 8; s8++) {
            float t0a = __shfl_sync(0xffffffffu, s[s8][0], src1);
            float t1a = __shfl_sync(0xffffffffu, s[s8][1], src1);
            float t2a = __shfl_sync(0xffffffffu, s[s8][2], src1);
            float t3a = __shfl_sync(0xffffffffu, s[s8][3], src1);
            float t0b = __shfl_sync(0xffffffffu, s[s8][0], src2);
            float t1b = __shfl_sync(0xffffffffu, s[s8][1], src2);
            float t2b = __shfl_sync(0xffffffffu, s[s8][2], src2);
            float t3b = __shfl_sync(0xffffffffu, s[s8][3], src2);
            uint4 pa;
            pa.x = f2tf(odd ? t1a : t0a);   // P(r4,    8*s8+cL)
            pa.y = f2tf(odd ? t3a : t2a);   // P(r4+8,  8*s8+cL)
            pa.z = f2tf(odd ? t1b : t0b);   // P(r4,    8*s8+cL+4)
            pa.w = f2tf(odd ? t3b : t2b);   // P(r4+8,  8*s8+cL+4)
#pragma unroll
            for (int dp = 0; dp < 4; dp++) {
                uint4 bq = ldsm_at(Vb + dp * 4096 + ofs[s8]);
                mma_tf32(Oa[2 * dp],     pa, bq.x, bq.z);
                mma_tf32(Oa[2 * dp + 1], pa, bq.y, bq.w);
            }
        }
        __syncthreads();
    }

    // epilogue: write tf32-rounded so the out-projection GEMM skips A-cvt
    const float i0 = 1.0f / l0, i1 = 1.0f / l1;
    float* op0 = g_attn + ((size_t)(b * SEQ) + q0 + 16 * w + r4) * EMB + h * HD;
    float* op1 = op0 + (size_t)8 * EMB;
#pragma unroll
    for (int ja = 0; ja < 8; ja++) {
        const int d = 8 * ja + c2;
        *(float2*)&op0[d] = make_float2(__uint_as_float(f2tf(Oa[ja][0] * i0)),
                                        __uint_as_float(f2tf(Oa[ja][1] * i0)));
        *(float2*)&op1[d] = make_float2(__uint_as_float(f2tf(Oa[ja][2] * i1)),
                                        __uint_as_float(f2tf(Oa[ja][3] * i1)));
    }
}

// ---------------- launch -----------------------------------------------------
extern "C" void kernel_launch(void* const* d_in, const int* in_sizes, int n_in,
                              void* d_out, int out_size)
{
    const float* q    = (const float*)d_in[0];
    const float* k    = (const float*)d_in[1];
    const float* v    = (const float*)d_in[2];
    const void*  mask = d_in[3];
    const float* Wq   = (const float*)d_in[4];
    const float* bq   = (const float*)d_in[5];
    const float* Wk   = (const float*)d_in[6];
    const float* bk   = (const float*)d_in[7];
    const float* Wv   = (const float*)d_in[8];
    const float* bv   = (const float*)d_in[9];
    const float* Wo   = (const float*)d_in[10];
    const float* bo   = (const float*)d_in[11];
    float* out = (float*)d_out;

    cudaFuncSetAttribute(gemm_qkv_kernel,
                         cudaFuncAttributeMaxDynamicSharedMemorySize, GEMM_SMEM);
    cudaFuncSetAttribute(gemm_out_kernel,
                         cudaFuncAttributeMaxDynamicSharedMemorySize, GEMM_SMEM);
    cudaFuncSetAttribute(attn_kernel,
                         cudaFuncAttributeMaxDynamicSharedMemorySize, ATT_SMEM);

    prep_mask_kernel<<<1, 1024>>>(mask);
    prep_weights_kernel<<<512, 256>>>(Wq, Wk, Wv, Wo);

    gemm_qkv_kernel<<<dim3(8, 32, 3), 256, GEMM_SMEM>>>(q, k, v, bq, bk, bv);

    attn_kernel<<<dim3(SEQ / 128, NH, BATCH), 256, ATT_SMEM>>>();

    gemm_out_kernel<<<dim3(8, 32, 1), 256, GEMM_SMEM>>>(bo, out);
}